// round 5
// baseline (speedup 1.0000x reference)
#include <cuda_runtime.h>
#include <cuda_bf16.h>
#include <cfloat>

#define BATCH 4
#define NPTS 4096
#define NUP 16384
#define CDIM 64
#define EPSV 1e-6f

// Spatial grid
#define GDIM 64
#define GCELLS (GDIM * GDIM * GDIM)     // 262144
#define TOTCELLS (BATCH * GCELLS)       // 1048576
#define GLO (-8.0f)
#define GH 0.25f
#define GINV 4.0f

// Scratch (__device__ globals; no cudaMalloc allowed)
__device__ float  g_G[BATCH * NPTS * CDIM];     // projected features F@W+b (4 MB)
__device__ int    g_cnt[TOTCELLS];              // histogram (4 MB)
__device__ int    g_start[TOTCELLS + 1];        // exclusive scan -> cell start
__device__ int    g_cur[TOTCELLS];              // scatter cursors
__device__ int    g_bsum[1024];                 // block sums for scan
__device__ float4 g_tpos[BATCH * NPTS];         // staged (x,y,z,|p|^2)
__device__ int    g_tcell[BATCH * NPTS];        // staged cell ids
__device__ float4 g_spos[BATCH * NPTS];         // cell-sorted positions
__device__ int    g_sidx[BATCH * NPTS];         // sorted -> original local idx
__device__ float4 g_w3[BATCH * NUP];            // normalized weights per query
__device__ int4   g_j3[BATCH * NUP];            // orig neighbor indices per query

// ---------------------------------------------------------------------------
// K0: zero histogram (must re-zero every launch: determinism)
// ---------------------------------------------------------------------------
__global__ void zero_cnt_kernel() {
    int i = blockIdx.x * blockDim.x + threadIdx.x;   // 262144 threads
    reinterpret_cast<int4*>(g_cnt)[i] = make_int4(0, 0, 0, 0);
}

// ---------------------------------------------------------------------------
// K1: histogram + stage pos4/cell
// ---------------------------------------------------------------------------
__device__ __forceinline__ int cell_coord(float v) {
    int c = (int)floorf((v - GLO) * GINV);
    return min(max(c, 0), GDIM - 1);
}

__global__ void hist_kernel(const float* __restrict__ pos) {
    int i = blockIdx.x * blockDim.x + threadIdx.x;   // 16384 threads
    int b = i >> 12;
    float x = pos[3 * i + 0];
    float y = pos[3 * i + 1];
    float z = pos[3 * i + 2];
    float n = x * x + y * y + z * z;
    g_tpos[i] = make_float4(x, y, z, n);
    int cx = cell_coord(x), cy = cell_coord(y), cz = cell_coord(z);
    int cell = b * GCELLS + ((cz * GDIM) + cy) * GDIM + cx;
    g_tcell[i] = cell;
    atomicAdd(&g_cnt[cell], 1);
}

// ---------------------------------------------------------------------------
// K2a/b/c: exclusive scan of g_cnt (1M elements) -> g_start, copy to g_cur
// ---------------------------------------------------------------------------
__device__ __forceinline__ int block_exscan_1024(int v, int* ws) {
    int lane = threadIdx.x & 31, w = threadIdx.x >> 5;
    int inc = v;
#pragma unroll
    for (int o = 1; o < 32; o <<= 1) {
        int n = __shfl_up_sync(0xffffffffu, inc, o);
        if (lane >= o) inc += n;
    }
    if (lane == 31) ws[w] = inc;
    __syncthreads();
    if (w == 0) {
        int t = ws[lane];
#pragma unroll
        for (int o = 1; o < 32; o <<= 1) {
            int n = __shfl_up_sync(0xffffffffu, t, o);
            if (lane >= o) t += n;
        }
        ws[lane] = t;            // inclusive warp sums
    }
    __syncthreads();
    return inc - v + (w > 0 ? ws[w - 1] : 0);   // exclusive within block
}

__global__ __launch_bounds__(1024) void scan_a_kernel() {
    __shared__ int ws[32];
    int g = blockIdx.x * 1024 + threadIdx.x;
    int v = g_cnt[g];
    int ex = block_exscan_1024(v, ws);
    g_start[g] = ex;
    if (threadIdx.x == 1023) g_bsum[blockIdx.x] = ex + v;
}

__global__ __launch_bounds__(1024) void scan_b_kernel() {
    __shared__ int ws[32];
    int v = g_bsum[threadIdx.x];
    int ex = block_exscan_1024(v, ws);
    g_bsum[threadIdx.x] = ex;
}

__global__ __launch_bounds__(1024) void scan_c_kernel() {
    int g = blockIdx.x * 1024 + threadIdx.x;
    int s = g_start[g] + g_bsum[blockIdx.x];
    g_start[g] = s;
    g_cur[g] = s;
    if (g == TOTCELLS - 1) g_start[TOTCELLS] = BATCH * NPTS;
}

// ---------------------------------------------------------------------------
// K3: scatter points into cell-sorted order
// ---------------------------------------------------------------------------
__global__ void scatter_kernel() {
    int i = blockIdx.x * blockDim.x + threadIdx.x;   // 16384 threads
    int c = g_tcell[i];
    int dst = atomicAdd(&g_cur[c], 1);
    g_spos[dst] = g_tpos[i];
    g_sidx[dst] = i & (NPTS - 1);
}

// ---------------------------------------------------------------------------
// K4: projection G = F @ W + b
// ---------------------------------------------------------------------------
#define PROJ_ROWS 32

__global__ __launch_bounds__(64) void proj_kernel(
    const float* __restrict__ feature,
    const float* __restrict__ W,
    const float* __restrict__ bias)
{
    __shared__ float frow[PROJ_ROWS * CDIM];
    const int d = threadIdx.x;
    const int row0 = blockIdx.x * PROJ_ROWS;

    float wcol[CDIM];
#pragma unroll
    for (int k = 0; k < CDIM; k++) wcol[k] = __ldg(&W[k * CDIM + d]);
    const float bd = __ldg(&bias[d]);

    const float* fsrc = feature + (size_t)row0 * CDIM;
    for (int i = threadIdx.x; i < PROJ_ROWS * CDIM; i += 64)
        frow[i] = fsrc[i];
    __syncthreads();

    for (int r = 0; r < PROJ_ROWS; r++) {
        float a0 = bd, a1 = 0.f, a2 = 0.f, a3 = 0.f;
        const float* fr = &frow[r * CDIM];
#pragma unroll
        for (int k = 0; k < CDIM; k += 4) {
            a0 = fmaf(fr[k + 0], wcol[k + 0], a0);
            a1 = fmaf(fr[k + 1], wcol[k + 1], a1);
            a2 = fmaf(fr[k + 2], wcol[k + 2], a2);
            a3 = fmaf(fr[k + 3], wcol[k + 3], a3);
        }
        g_G[(size_t)(row0 + r) * CDIM + d] = (a0 + a1) + (a2 + a3);
    }
}

// ---------------------------------------------------------------------------
// 3-NN insert
// ---------------------------------------------------------------------------
__device__ __forceinline__ void ins3(float s, int idx,
                                     float& d0, float& d1, float& d2,
                                     int& i0, int& i1, int& i2)
{
    if (s < d2) {
        if (s < d1) {
            d2 = d1; i2 = i1;
            if (s < d0) { d1 = d0; i1 = i0; d0 = s; i0 = idx; }
            else        { d1 = s;  i1 = idx; }
        } else {
            d2 = s; i2 = idx;
        }
    }
}

// ---------------------------------------------------------------------------
// K5: exact 3-NN via expanding Chebyshev shells over the grid.
// After scanning cube radius r, any unscanned point is >= r*h away.
// ---------------------------------------------------------------------------
__global__ __launch_bounds__(128) void query_kernel(
    const float* __restrict__ pos_up)
{
    const int b = blockIdx.y;
    const int ql = blockIdx.x * 128 + threadIdx.x;
    const int q = b * NUP + ql;

    const float qx = pos_up[3 * q + 0];
    const float qy = pos_up[3 * q + 1];
    const float qz = pos_up[3 * q + 2];
    const float qn = qx * qx + qy * qy + qz * qz;
    const float qx2 = -2.0f * qx, qy2 = -2.0f * qy, qz2 = -2.0f * qz;

    const int cx = cell_coord(qx), cy = cell_coord(qy), cz = cell_coord(qz);

    float d0 = FLT_MAX, d1 = FLT_MAX, d2 = FLT_MAX;
    int   i0 = 0, i1 = 0, i2 = 0;

    int r = 0;
    while (true) {
        // scan shell at Chebyshev radius r
        const int zl = cz - r, zh = cz + r;
        for (int z = max(zl, 0); z <= min(zh, GDIM - 1); z++) {
            const bool ze = (z == zl) || (z == zh);
            const int yl = cy - r, yh = cy + r;
            for (int y = max(yl, 0); y <= min(yh, GDIM - 1); y++) {
                const bool edge = ze || (y == yl) || (y == yh);
                const int rowbase = b * GCELLS + ((z * GDIM) + y) * GDIM;
                if (edge) {
                    const int xl = max(cx - r, 0), xh = min(cx + r, GDIM - 1);
                    const int s = __ldg(&g_start[rowbase + xl]);
                    const int e = __ldg(&g_start[rowbase + xh + 1]);
                    for (int i = s; i < e; i++) {
                        float4 p = __ldg(&g_spos[i]);
                        float sv = fmaf(qx2, p.x, fmaf(qy2, p.y, fmaf(qz2, p.z, p.w)));
                        ins3(sv, i, d0, d1, d2, i0, i1, i2);
                    }
                } else {
                    const int xa = cx - r;
                    if (xa >= 0) {
                        const int s = __ldg(&g_start[rowbase + xa]);
                        const int e = __ldg(&g_start[rowbase + xa + 1]);
                        for (int i = s; i < e; i++) {
                            float4 p = __ldg(&g_spos[i]);
                            float sv = fmaf(qx2, p.x, fmaf(qy2, p.y, fmaf(qz2, p.z, p.w)));
                            ins3(sv, i, d0, d1, d2, i0, i1, i2);
                        }
                    }
                    const int xb = cx + r;
                    if (xb < GDIM) {
                        const int s = __ldg(&g_start[rowbase + xb]);
                        const int e = __ldg(&g_start[rowbase + xb + 1]);
                        for (int i = s; i < e; i++) {
                            float4 p = __ldg(&g_spos[i]);
                            float sv = fmaf(qx2, p.x, fmaf(qy2, p.y, fmaf(qz2, p.z, p.w)));
                            ins3(sv, i, d0, d1, d2, i0, i1, i2);
                        }
                    }
                }
            }
        }
        // stop: true d3 (= d2 + qn) within guaranteed-scanned radius r*h
        const float rb = (float)r * GH;
        if (d2 + qn <= rb * rb * 0.99999f) break;
        if (r >= GDIM) break;     // cube covers whole grid
        r++;
    }

    // weights: w = 1/(d^2 + eps), normalized
    float w0 = 1.0f / ((d0 + qn) + EPSV);
    float w1 = 1.0f / ((d1 + qn) + EPSV);
    float w2 = 1.0f / ((d2 + qn) + EPSV);
    float inv = 1.0f / (w0 + w1 + w2);
    g_w3[q] = make_float4(w0 * inv, w1 * inv, w2 * inv, 0.f);
    g_j3[q] = make_int4(g_sidx[i0], g_sidx[i1], g_sidx[i2], 0);
}

// ---------------------------------------------------------------------------
// K6: apply — 4 threads per query, coalesced blend of 3 G rows + ReLU
// ---------------------------------------------------------------------------
__global__ __launch_bounds__(256) void apply_kernel(float* __restrict__ out)
{
    const int t = blockIdx.x * 256 + threadIdx.x;    // 262144 threads
    const int q = t >> 2;                            // global query
    const int sub = t & 3;
    const int b = q >> 14;

    const float4 w = g_w3[q];
    const int4   j = g_j3[q];

    const float4* G4 = reinterpret_cast<const float4*>(g_G);
    const float4* r0 = G4 + (size_t)(b * NPTS + j.x) * (CDIM / 4) + sub * 4;
    const float4* r1 = G4 + (size_t)(b * NPTS + j.y) * (CDIM / 4) + sub * 4;
    const float4* r2 = G4 + (size_t)(b * NPTS + j.z) * (CDIM / 4) + sub * 4;
    float4* out4 = reinterpret_cast<float4*>(out) + (size_t)q * (CDIM / 4) + sub * 4;

#pragma unroll
    for (int k = 0; k < 4; k++) {
        float4 a = __ldg(&r0[k]);
        float4 c = __ldg(&r1[k]);
        float4 e = __ldg(&r2[k]);
        float4 o;
        o.x = fmaxf(0.f, fmaf(w.x, a.x, fmaf(w.y, c.x, w.z * e.x)));
        o.y = fmaxf(0.f, fmaf(w.x, a.y, fmaf(w.y, c.y, w.z * e.y)));
        o.z = fmaxf(0.f, fmaf(w.x, a.z, fmaf(w.y, c.z, w.z * e.z)));
        o.w = fmaxf(0.f, fmaf(w.x, a.w, fmaf(w.y, c.w, w.z * e.w)));
        out4[k] = o;
    }
}

// ---------------------------------------------------------------------------
extern "C" void kernel_launch(void* const* d_in, const int* in_sizes, int n_in,
                              void* d_out, int out_size)
{
    const float* feature = (const float*)d_in[0];   // (4, 4096, 64)
    const float* pos     = (const float*)d_in[1];   // (4, 4096, 3)
    const float* pos_up  = (const float*)d_in[2];   // (4, 16384, 3)
    const float* W       = (const float*)d_in[3];   // (64, 64)
    const float* bias    = (const float*)d_in[4];   // (64,)
    float* out = (float*)d_out;                     // (4, 16384, 64)

    zero_cnt_kernel<<<TOTCELLS / 4 / 1024, 1024>>>();
    hist_kernel<<<BATCH * NPTS / 256, 256>>>(pos);
    proj_kernel<<<BATCH * NPTS / PROJ_ROWS, 64>>>(feature, W, bias);
    scan_a_kernel<<<TOTCELLS / 1024, 1024>>>();
    scan_b_kernel<<<1, 1024>>>();
    scan_c_kernel<<<TOTCELLS / 1024, 1024>>>();
    scatter_kernel<<<BATCH * NPTS / 256, 256>>>();

    dim3 qgrid(NUP / 128, BATCH);
    query_kernel<<<qgrid, 128>>>(pos_up);

    apply_kernel<<<BATCH * NUP * 4 / 256, 256>>>(out);
}

// round 6
// speedup vs baseline: 1.6168x; 1.6168x over previous
#include <cuda_runtime.h>
#include <cuda_bf16.h>
#include <cfloat>

#define BATCH 4
#define NPTS 4096
#define NUP 16384
#define CDIM 64
#define EPSV 1e-6f

// Spatial grid: [-5,5]^3, h=0.25
#define GDIM 40
#define GCELLS (GDIM * GDIM * GDIM)     // 64000
#define TOTCELLS (BATCH * GCELLS)       // 256000
#define GLO (-5.0f)
#define GH 0.25f
#define GINV 4.0f
#define SCANB (TOTCELLS / 1024)         // 250

#define ULLMAX 0xFFFFFFFFFFFFFFFFull

// Scratch (__device__ globals; no cudaMalloc allowed)
__device__ float  g_G[BATCH * NPTS * CDIM];     // projected features F@W+b (4 MB)
__device__ int    g_cnt[TOTCELLS];              // histogram
__device__ int    g_start[TOTCELLS + 1];        // exclusive scan -> cell start
__device__ int    g_cur[TOTCELLS];              // scatter cursors
__device__ int    g_bsum[1024];                 // block sums for scan
__device__ float4 g_tpos[BATCH * NPTS];         // staged (x,y,z,|p|^2)
__device__ int    g_tcell[BATCH * NPTS];        // staged cell ids
__device__ float4 g_spos[BATCH * NPTS];         // cell-sorted positions
__device__ int    g_sidx[BATCH * NPTS];         // sorted -> original local idx
__device__ float4 g_w3[BATCH * NUP];            // normalized weights per query
__device__ int4   g_j3[BATCH * NUP];            // orig neighbor indices per query

// ---------------------------------------------------------------------------
__global__ void zero_cnt_kernel() {
    int i = blockIdx.x * blockDim.x + threadIdx.x;   // TOTCELLS/4 threads
    reinterpret_cast<int4*>(g_cnt)[i] = make_int4(0, 0, 0, 0);
}

__device__ __forceinline__ int cell_coord(float v) {
    int c = (int)floorf((v - GLO) * GINV);
    return min(max(c, 0), GDIM - 1);
}

__global__ void hist_kernel(const float* __restrict__ pos) {
    int i = blockIdx.x * blockDim.x + threadIdx.x;   // 16384 threads
    int b = i >> 12;
    float x = pos[3 * i + 0];
    float y = pos[3 * i + 1];
    float z = pos[3 * i + 2];
    float n = x * x + y * y + z * z;
    g_tpos[i] = make_float4(x, y, z, n);
    int cx = cell_coord(x), cy = cell_coord(y), cz = cell_coord(z);
    int cell = b * GCELLS + ((cz * GDIM) + cy) * GDIM + cx;
    g_tcell[i] = cell;
    atomicAdd(&g_cnt[cell], 1);
}

// ---------------------------------------------------------------------------
// exclusive scan of g_cnt (256000) -> g_start (+ copy to g_cur)
// ---------------------------------------------------------------------------
__device__ __forceinline__ int block_exscan_1024(int v, int* ws) {
    int lane = threadIdx.x & 31, w = threadIdx.x >> 5;
    int inc = v;
#pragma unroll
    for (int o = 1; o < 32; o <<= 1) {
        int n = __shfl_up_sync(0xffffffffu, inc, o);
        if (lane >= o) inc += n;
    }
    if (lane == 31) ws[w] = inc;
    __syncthreads();
    if (w == 0) {
        int t = ws[lane];
#pragma unroll
        for (int o = 1; o < 32; o <<= 1) {
            int n = __shfl_up_sync(0xffffffffu, t, o);
            if (lane >= o) t += n;
        }
        ws[lane] = t;
    }
    __syncthreads();
    return inc - v + (w > 0 ? ws[w - 1] : 0);
}

__global__ __launch_bounds__(1024) void scan_a_kernel() {
    __shared__ int ws[32];
    int g = blockIdx.x * 1024 + threadIdx.x;
    int v = g_cnt[g];
    int ex = block_exscan_1024(v, ws);
    g_start[g] = ex;
    if (threadIdx.x == 1023) g_bsum[blockIdx.x] = ex + v;
}

__global__ __launch_bounds__(1024) void scan_b_kernel() {
    __shared__ int ws[32];
    int v = (threadIdx.x < SCANB) ? g_bsum[threadIdx.x] : 0;
    int ex = block_exscan_1024(v, ws);
    if (threadIdx.x < SCANB) g_bsum[threadIdx.x] = ex;
}

__global__ __launch_bounds__(1024) void scan_c_kernel() {
    int g = blockIdx.x * 1024 + threadIdx.x;
    int s = g_start[g] + g_bsum[blockIdx.x];
    g_start[g] = s;
    g_cur[g] = s;
    if (g == TOTCELLS - 1) g_start[TOTCELLS] = BATCH * NPTS;
}

__global__ void scatter_kernel() {
    int i = blockIdx.x * blockDim.x + threadIdx.x;   // 16384 threads
    int c = g_tcell[i];
    int dst = atomicAdd(&g_cur[c], 1);
    g_spos[dst] = g_tpos[i];
    g_sidx[dst] = i & (NPTS - 1);
}

// ---------------------------------------------------------------------------
// projection G = F @ W + b
// ---------------------------------------------------------------------------
#define PROJ_ROWS 32

__global__ __launch_bounds__(64) void proj_kernel(
    const float* __restrict__ feature,
    const float* __restrict__ W,
    const float* __restrict__ bias)
{
    __shared__ float frow[PROJ_ROWS * CDIM];
    const int d = threadIdx.x;
    const int row0 = blockIdx.x * PROJ_ROWS;

    float wcol[CDIM];
#pragma unroll
    for (int k = 0; k < CDIM; k++) wcol[k] = __ldg(&W[k * CDIM + d]);
    const float bd = __ldg(&bias[d]);

    const float* fsrc = feature + (size_t)row0 * CDIM;
    for (int i = threadIdx.x; i < PROJ_ROWS * CDIM; i += 64)
        frow[i] = fsrc[i];
    __syncthreads();

    for (int r = 0; r < PROJ_ROWS; r++) {
        float a0 = bd, a1 = 0.f, a2 = 0.f, a3 = 0.f;
        const float* fr = &frow[r * CDIM];
#pragma unroll
        for (int k = 0; k < CDIM; k += 4) {
            a0 = fmaf(fr[k + 0], wcol[k + 0], a0);
            a1 = fmaf(fr[k + 1], wcol[k + 1], a1);
            a2 = fmaf(fr[k + 2], wcol[k + 2], a2);
            a3 = fmaf(fr[k + 3], wcol[k + 3], a3);
        }
        g_G[(size_t)(row0 + r) * CDIM + d] = (a0 + a1) + (a2 + a3);
    }
}

// ---------------------------------------------------------------------------
// Query: WARP-PER-QUERY exact 3-NN. Lanes split cube cells; per-lane top-3
// kept as packed u64 keys (branchless); warp merge via 3x min-reduce+pop.
// Expansion decisions are warp-uniform (no divergent shell walks).
// key = (monotone(float_bits(s)) << 16) | sorted_point_index
// ---------------------------------------------------------------------------
__global__ __launch_bounds__(256) void query_kernel(
    const float* __restrict__ pos_up)
{
    const int lane = threadIdx.x & 31;
    const int q = blockIdx.x * 8 + (threadIdx.x >> 5);   // 0..65535
    const int b = q >> 14;

    const float qx = __ldg(&pos_up[3 * q + 0]);
    const float qy = __ldg(&pos_up[3 * q + 1]);
    const float qz = __ldg(&pos_up[3 * q + 2]);
    const float qn = qx * qx + qy * qy + qz * qz;
    const float qx2 = -2.0f * qx, qy2 = -2.0f * qy, qz2 = -2.0f * qz;

    const int cx = cell_coord(qx), cy = cell_coord(qy), cz = cell_coord(qz);

    unsigned long long best0 = ULLMAX, best1 = ULLMAX, best2 = ULLMAX;

    int r = 1;
    while (true) {
        unsigned long long k0 = ULLMAX, k1 = ULLMAX, k2 = ULLMAX;

        const int xlo = max(cx - r, 0), xhi = min(cx + r, GDIM - 1);
        const int ylo = max(cy - r, 0), yhi = min(cy + r, GDIM - 1);
        const int zlo = max(cz - r, 0), zhi = min(cz + r, GDIM - 1);
        const int nx = xhi - xlo + 1, ny = yhi - ylo + 1, nz = zhi - zlo + 1;
        const int nxy = nx * ny;
        const int total = nxy * nz;

        for (int t = lane; t < total; t += 32) {
            const int tz = t / nxy;
            const int rem = t - tz * nxy;
            const int ty = rem / nx;
            const int tx = rem - ty * nx;
            const int cell = b * GCELLS + (((zlo + tz) * GDIM) + (ylo + ty)) * GDIM + (xlo + tx);
            const int s = __ldg(&g_start[cell]);
            const int e = __ldg(&g_start[cell + 1]);
            for (int i = s; i < e; i++) {
                float4 p = __ldg(&g_spos[i]);
                float sv = fmaf(qx2, p.x, fmaf(qy2, p.y, fmaf(qz2, p.z, p.w)));
                unsigned fb = __float_as_uint(sv);
                unsigned mm = ((unsigned)((int)fb >> 31)) | 0x80000000u;
                unsigned long long key =
                    ((unsigned long long)(fb ^ mm) << 16) | (unsigned)i;
                // branchless sorted-triple insert
                unsigned long long t1 = (k1 > key) ? k1 : key;
                unsigned long long t0 = (k0 > key) ? k0 : key;
                k2 = (k2 < t1) ? k2 : t1;
                k1 = (k1 < t0) ? k1 : t0;
                k0 = (k0 < key) ? k0 : key;
            }
        }

        // warp merge: 3 rounds of min-reduce + pop
        unsigned long long a0 = k0, a1 = k1, a2 = k2;
#pragma unroll
        for (int tsel = 0; tsel < 3; tsel++) {
            unsigned long long m = a0;
#pragma unroll
            for (int o = 16; o; o >>= 1) {
                unsigned long long oth = __shfl_xor_sync(0xffffffffu, m, o);
                m = (oth < m) ? oth : m;
            }
            if (tsel == 0) best0 = m;
            else if (tsel == 1) best1 = m;
            else best2 = m;
            if (a0 == m) { a0 = a1; a1 = a2; a2 = ULLMAX; }
        }

        // stopping bound: nearest unscanned point >= min dist to unclipped face
        unsigned ub = (unsigned)(best2 >> 16);
        unsigned fb = ub ^ ((ub & 0x80000000u) ? 0x80000000u : 0xFFFFFFFFu);
        float d3 = __uint_as_float(fb) + qn;          // true squared dist of 3rd NN

        float rb = FLT_MAX;
        bool covered = true;
        if (cx - r > 0)        { rb = fminf(rb, qx - (GLO + (cx - r) * GH));     covered = false; }
        if (cx + r < GDIM - 1) { rb = fminf(rb, (GLO + (cx + r + 1) * GH) - qx); covered = false; }
        if (cy - r > 0)        { rb = fminf(rb, qy - (GLO + (cy - r) * GH));     covered = false; }
        if (cy + r < GDIM - 1) { rb = fminf(rb, (GLO + (cy + r + 1) * GH) - qy); covered = false; }
        if (cz - r > 0)        { rb = fminf(rb, qz - (GLO + (cz - r) * GH));     covered = false; }
        if (cz + r < GDIM - 1) { rb = fminf(rb, (GLO + (cz + r + 1) * GH) - qz); covered = false; }

        if (covered) break;                            // whole grid scanned
        if (d3 <= rb * rb * 0.99999f) break;           // provably exact (NaN -> expand)
        r++;
    }

    if (lane == 0) {
        unsigned u0 = (unsigned)(best0 >> 16);
        unsigned u1 = (unsigned)(best1 >> 16);
        unsigned u2 = (unsigned)(best2 >> 16);
        float s0 = __uint_as_float(u0 ^ ((u0 & 0x80000000u) ? 0x80000000u : 0xFFFFFFFFu));
        float s1 = __uint_as_float(u1 ^ ((u1 & 0x80000000u) ? 0x80000000u : 0xFFFFFFFFu));
        float s2 = __uint_as_float(u2 ^ ((u2 & 0x80000000u) ? 0x80000000u : 0xFFFFFFFFu));
        float w0 = 1.0f / ((s0 + qn) + EPSV);
        float w1 = 1.0f / ((s1 + qn) + EPSV);
        float w2 = 1.0f / ((s2 + qn) + EPSV);
        float inv = 1.0f / (w0 + w1 + w2);
        g_w3[q] = make_float4(w0 * inv, w1 * inv, w2 * inv, 0.f);
        int p0 = g_sidx[best0 & 0xFFFF];
        int p1 = g_sidx[best1 & 0xFFFF];
        int p2 = g_sidx[best2 & 0xFFFF];
        g_j3[q] = make_int4(p0, p1, p2, 0);
    }
}

// ---------------------------------------------------------------------------
// apply: 4 threads per query, coalesced blend of 3 G rows + ReLU
// ---------------------------------------------------------------------------
__global__ __launch_bounds__(256) void apply_kernel(float* __restrict__ out)
{
    const int t = blockIdx.x * 256 + threadIdx.x;    // 262144 threads
    const int q = t >> 2;
    const int sub = t & 3;
    const int b = q >> 14;

    const float4 w = g_w3[q];
    const int4   j = g_j3[q];

    const float4* G4 = reinterpret_cast<const float4*>(g_G);
    const float4* r0 = G4 + (size_t)(b * NPTS + j.x) * (CDIM / 4) + sub * 4;
    const float4* r1 = G4 + (size_t)(b * NPTS + j.y) * (CDIM / 4) + sub * 4;
    const float4* r2 = G4 + (size_t)(b * NPTS + j.z) * (CDIM / 4) + sub * 4;
    float4* out4 = reinterpret_cast<float4*>(out) + (size_t)q * (CDIM / 4) + sub * 4;

#pragma unroll
    for (int k = 0; k < 4; k++) {
        float4 a = __ldg(&r0[k]);
        float4 c = __ldg(&r1[k]);
        float4 e = __ldg(&r2[k]);
        float4 o;
        o.x = fmaxf(0.f, fmaf(w.x, a.x, fmaf(w.y, c.x, w.z * e.x)));
        o.y = fmaxf(0.f, fmaf(w.x, a.y, fmaf(w.y, c.y, w.z * e.y)));
        o.z = fmaxf(0.f, fmaf(w.x, a.z, fmaf(w.y, c.z, w.z * e.z)));
        o.w = fmaxf(0.f, fmaf(w.x, a.w, fmaf(w.y, c.w, w.z * e.w)));
        out4[k] = o;
    }
}

// ---------------------------------------------------------------------------
extern "C" void kernel_launch(void* const* d_in, const int* in_sizes, int n_in,
                              void* d_out, int out_size)
{
    const float* feature = (const float*)d_in[0];   // (4, 4096, 64)
    const float* pos     = (const float*)d_in[1];   // (4, 4096, 3)
    const float* pos_up  = (const float*)d_in[2];   // (4, 16384, 3)
    const float* W       = (const float*)d_in[3];   // (64, 64)
    const float* bias    = (const float*)d_in[4];   // (64,)
    float* out = (float*)d_out;                     // (4, 16384, 64)

    zero_cnt_kernel<<<TOTCELLS / 4 / 256, 256>>>();
    hist_kernel<<<BATCH * NPTS / 256, 256>>>(pos);
    proj_kernel<<<BATCH * NPTS / PROJ_ROWS, 64>>>(feature, W, bias);
    scan_a_kernel<<<TOTCELLS / 1024, 1024>>>();
    scan_b_kernel<<<1, 1024>>>();
    scan_c_kernel<<<TOTCELLS / 1024, 1024>>>();
    scatter_kernel<<<BATCH * NPTS / 256, 256>>>();

    query_kernel<<<BATCH * NUP / 8, 256>>>(pos_up);

    apply_kernel<<<BATCH * NUP * 4 / 256, 256>>>(out);
}

// round 7
// speedup vs baseline: 2.0071x; 1.2414x over previous
#include <cuda_runtime.h>
#include <cuda_bf16.h>
#include <cfloat>

#define BATCH 4
#define NPTS 4096
#define NUP 16384
#define CDIM 64
#define EPSV 1e-6f

// Spatial grid: [-5,5]^3, h=0.25
#define GDIM 40
#define GCELLS (GDIM * GDIM * GDIM)     // 64000
#define TOTCELLS (BATCH * GCELLS)       // 256000
#define GLO (-5.0f)
#define GH 0.25f
#define GINV 4.0f
#define SCANB (TOTCELLS / 1024)         // 250

// Scratch (__device__ globals; no cudaMalloc allowed)
__device__ float  g_G[BATCH * NPTS * CDIM];     // projected features F@W+b (4 MB)
__device__ int    g_cnt2[2][TOTCELLS];          // histograms: [0]=points [1]=queries
__device__ int    g_start2[2][TOTCELLS + 1];    // exclusive scans
__device__ int    g_cur2[2][TOTCELLS];          // scatter cursors
__device__ int    g_bsum2[2][256];              // block sums
__device__ float4 g_tpos[BATCH * NPTS];         // staged point (x,y,z,|p|^2)
__device__ int    g_tcell[BATCH * NPTS];
__device__ float4 g_qpos[BATCH * NUP];          // staged query (x,y,z,|q|^2)
__device__ int    g_qcell[BATCH * NUP];
__device__ float4 g_spos[BATCH * NPTS];         // cell-sorted points
__device__ int    g_sidx[BATCH * NPTS];         // sorted -> original local idx
__device__ float4 g_sqpos[BATCH * NUP];         // cell-sorted queries
__device__ int    g_sqid[BATCH * NUP];          // sorted -> original global qid
__device__ float4 g_w3[BATCH * NUP];            // normalized weights (by orig qid)
__device__ int4   g_j3[BATCH * NUP];            // neighbor orig indices (by orig qid)

__device__ __forceinline__ int cell_coord(float v) {
    int c = (int)floorf((v - GLO) * GINV);
    return min(max(c, 0), GDIM - 1);
}

// ---------------------------------------------------------------------------
// K0: zero both histograms (2*TOTCELLS ints, int4 stores) — 500 blocks x 256
// ---------------------------------------------------------------------------
__global__ void zero_cnt_kernel() {
    int i = blockIdx.x * blockDim.x + threadIdx.x;     // 128000 threads
    reinterpret_cast<int4*>(&g_cnt2[0][0])[i] = make_int4(0, 0, 0, 0);
}

// ---------------------------------------------------------------------------
// K1: histogram + stage for BOTH points (blocks [0,64)) and queries [64,320)
// ---------------------------------------------------------------------------
__global__ void hist_both_kernel(const float* __restrict__ pos,
                                 const float* __restrict__ pos_up) {
    int t = blockIdx.x * 256 + threadIdx.x;
    if (blockIdx.x < 64) {                 // points: t in [0, 16384)
        int i = t;
        int b = i >> 12;
        float x = pos[3 * i + 0];
        float y = pos[3 * i + 1];
        float z = pos[3 * i + 2];
        float n = x * x + y * y + z * z;
        g_tpos[i] = make_float4(x, y, z, n);
        int cell = b * GCELLS + ((cell_coord(z) * GDIM) + cell_coord(y)) * GDIM + cell_coord(x);
        g_tcell[i] = cell;
        atomicAdd(&g_cnt2[0][cell], 1);
    } else {                               // queries: i in [0, 65536)
        int i = t - 16384;
        int b = i >> 14;
        float x = pos_up[3 * i + 0];
        float y = pos_up[3 * i + 1];
        float z = pos_up[3 * i + 2];
        float n = x * x + y * y + z * z;
        g_qpos[i] = make_float4(x, y, z, n);
        int cell = b * GCELLS + ((cell_coord(z) * GDIM) + cell_coord(y)) * GDIM + cell_coord(x);
        g_qcell[i] = cell;
        atomicAdd(&g_cnt2[1][cell], 1);
    }
}

// ---------------------------------------------------------------------------
// K2a/b/c: exclusive scans of both histograms
// ---------------------------------------------------------------------------
__device__ __forceinline__ int block_exscan_1024(int v, int* ws) {
    int lane = threadIdx.x & 31, w = threadIdx.x >> 5;
    int inc = v;
#pragma unroll
    for (int o = 1; o < 32; o <<= 1) {
        int n = __shfl_up_sync(0xffffffffu, inc, o);
        if (lane >= o) inc += n;
    }
    if (lane == 31) ws[w] = inc;
    __syncthreads();
    if (w == 0) {
        int t = ws[lane];
#pragma unroll
        for (int o = 1; o < 32; o <<= 1) {
            int n = __shfl_up_sync(0xffffffffu, t, o);
            if (lane >= o) t += n;
        }
        ws[lane] = t;
    }
    __syncthreads();
    return inc - v + (w > 0 ? ws[w - 1] : 0);
}

__global__ __launch_bounds__(1024) void scan_a_kernel() {   // grid 500
    __shared__ int ws[32];
    int ab = blockIdx.x >= SCANB;
    int blk = blockIdx.x - ab * SCANB;
    int g = blk * 1024 + threadIdx.x;
    int v = g_cnt2[ab][g];
    int ex = block_exscan_1024(v, ws);
    g_start2[ab][g] = ex;
    if (threadIdx.x == 1023) g_bsum2[ab][blk] = ex + v;
}

__global__ __launch_bounds__(1024) void scan_b_kernel() {   // grid 2
    __shared__ int ws[32];
    int ab = blockIdx.x;
    int v = (threadIdx.x < SCANB) ? g_bsum2[ab][threadIdx.x] : 0;
    int ex = block_exscan_1024(v, ws);
    if (threadIdx.x < SCANB) g_bsum2[ab][threadIdx.x] = ex;
}

__global__ __launch_bounds__(1024) void scan_c_kernel() {   // grid 500
    int ab = blockIdx.x >= SCANB;
    int blk = blockIdx.x - ab * SCANB;
    int g = blk * 1024 + threadIdx.x;
    int s = g_start2[ab][g] + g_bsum2[ab][blk];
    g_start2[ab][g] = s;
    g_cur2[ab][g] = s;
    if (g == TOTCELLS - 1)
        g_start2[ab][TOTCELLS] = ab ? (BATCH * NUP) : (BATCH * NPTS);
}

// ---------------------------------------------------------------------------
// K3: scatter both into cell-sorted order
// ---------------------------------------------------------------------------
__global__ void scatter_both_kernel() {
    int t = blockIdx.x * 256 + threadIdx.x;
    if (blockIdx.x < 64) {
        int i = t;
        int dst = atomicAdd(&g_cur2[0][g_tcell[i]], 1);
        g_spos[dst] = g_tpos[i];
        g_sidx[dst] = i & (NPTS - 1);
    } else {
        int i = t - 16384;
        int dst = atomicAdd(&g_cur2[1][g_qcell[i]], 1);
        g_sqpos[dst] = g_qpos[i];
        g_sqid[dst] = i;
    }
}

// ---------------------------------------------------------------------------
// K4: projection G = F @ W + b
// ---------------------------------------------------------------------------
#define PROJ_ROWS 32

__global__ __launch_bounds__(64) void proj_kernel(
    const float* __restrict__ feature,
    const float* __restrict__ W,
    const float* __restrict__ bias)
{
    __shared__ float frow[PROJ_ROWS * CDIM];
    const int d = threadIdx.x;
    const int row0 = blockIdx.x * PROJ_ROWS;

    float wcol[CDIM];
#pragma unroll
    for (int k = 0; k < CDIM; k++) wcol[k] = __ldg(&W[k * CDIM + d]);
    const float bd = __ldg(&bias[d]);

    const float* fsrc = feature + (size_t)row0 * CDIM;
    for (int i = threadIdx.x; i < PROJ_ROWS * CDIM; i += 64)
        frow[i] = fsrc[i];
    __syncthreads();

    for (int r = 0; r < PROJ_ROWS; r++) {
        float a0 = bd, a1 = 0.f, a2 = 0.f, a3 = 0.f;
        const float* fr = &frow[r * CDIM];
#pragma unroll
        for (int k = 0; k < CDIM; k += 4) {
            a0 = fmaf(fr[k + 0], wcol[k + 0], a0);
            a1 = fmaf(fr[k + 1], wcol[k + 1], a1);
            a2 = fmaf(fr[k + 2], wcol[k + 2], a2);
            a3 = fmaf(fr[k + 3], wcol[k + 3], a3);
        }
        g_G[(size_t)(row0 + r) * CDIM + d] = (a0 + a1) + (a2 + a3);
    }
}

// ---------------------------------------------------------------------------
__device__ __forceinline__ void ins3(float s, int idx,
                                     float& d0, float& d1, float& d2,
                                     int& i0, int& i1, int& i2)
{
    if (s < d2) {
        if (s < d1) {
            d2 = d1; i2 = i1;
            if (s < d0) { d1 = d0; i1 = i0; d0 = s; i0 = idx; }
            else        { d1 = s;  i1 = idx; }
        } else {
            d2 = s; i2 = idx;
        }
    }
}

// ---------------------------------------------------------------------------
// K5: thread-per-query 3-NN over SORTED queries (warp-coherent walks).
// Cube rows are x-contiguous point ranges: 2 LDGs per (z,y) row.
// Expansion = reset + full rescan (no duplicate inserts); exact stop rule.
// ---------------------------------------------------------------------------
__global__ __launch_bounds__(256) void query_kernel()
{
    const int t = blockIdx.x * 256 + threadIdx.x;     // 0..65535 (sorted order)
    const float4 qp = g_sqpos[t];
    const int qid = g_sqid[t];
    const int b = qid >> 14;

    const float qx = qp.x, qy = qp.y, qz = qp.z, qn = qp.w;
    const float qx2 = -2.0f * qx, qy2 = -2.0f * qy, qz2 = -2.0f * qz;
    const int cx = cell_coord(qx), cy = cell_coord(qy), cz = cell_coord(qz);

    float d0, d1, d2;
    int   i0 = 0, i1 = 0, i2 = 0;

    int r = 1;
    while (true) {
        d0 = FLT_MAX; d1 = FLT_MAX; d2 = FLT_MAX;
        const int xlo = max(cx - r, 0), xhi = min(cx + r, GDIM - 1);
        const int ylo = max(cy - r, 0), yhi = min(cy + r, GDIM - 1);
        const int zlo = max(cz - r, 0), zhi = min(cz + r, GDIM - 1);

        for (int z = zlo; z <= zhi; z++) {
            for (int y = ylo; y <= yhi; y++) {
                const int row = b * GCELLS + ((z * GDIM) + y) * GDIM;
                const int s = __ldg(&g_start2[0][row + xlo]);
                const int e = __ldg(&g_start2[0][row + xhi + 1]);
                for (int i = s; i < e; i++) {
                    float4 p = __ldg(&g_spos[i]);
                    float sv = fmaf(qx2, p.x, fmaf(qy2, p.y, fmaf(qz2, p.z, p.w)));
                    if (sv < d2) ins3(sv, i, d0, d1, d2, i0, i1, i2);
                }
            }
        }

        // stop: 3rd-NN true dist within distance to nearest unclipped cube face
        float rb = FLT_MAX;
        bool covered = true;
        if (cx - r > 0)        { rb = fminf(rb, qx - (GLO + (cx - r) * GH));     covered = false; }
        if (cx + r < GDIM - 1) { rb = fminf(rb, (GLO + (cx + r + 1) * GH) - qx); covered = false; }
        if (cy - r > 0)        { rb = fminf(rb, qy - (GLO + (cy - r) * GH));     covered = false; }
        if (cy + r < GDIM - 1) { rb = fminf(rb, (GLO + (cy + r + 1) * GH) - qy); covered = false; }
        if (cz - r > 0)        { rb = fminf(rb, qz - (GLO + (cz - r) * GH));     covered = false; }
        if (cz + r < GDIM - 1) { rb = fminf(rb, (GLO + (cz + r + 1) * GH) - qz); covered = false; }

        if (covered) break;
        if (d2 + qn <= rb * rb * 0.99999f) break;
        r++;
    }

    float w0 = 1.0f / ((d0 + qn) + EPSV);
    float w1 = 1.0f / ((d1 + qn) + EPSV);
    float w2 = 1.0f / ((d2 + qn) + EPSV);
    float inv = 1.0f / (w0 + w1 + w2);
    g_w3[qid] = make_float4(w0 * inv, w1 * inv, w2 * inv, 0.f);
    g_j3[qid] = make_int4(g_sidx[i0], g_sidx[i1], g_sidx[i2], 0);
}

// ---------------------------------------------------------------------------
// K6: apply — 4 threads per query, coalesced blend of 3 G rows + ReLU
// ---------------------------------------------------------------------------
__global__ __launch_bounds__(256) void apply_kernel(float* __restrict__ out)
{
    const int t = blockIdx.x * 256 + threadIdx.x;    // 262144 threads
    const int q = t >> 2;
    const int sub = t & 3;
    const int b = q >> 14;

    const float4 w = g_w3[q];
    const int4   j = g_j3[q];

    const float4* G4 = reinterpret_cast<const float4*>(g_G);
    const float4* r0 = G4 + (size_t)(b * NPTS + j.x) * (CDIM / 4) + sub * 4;
    const float4* r1 = G4 + (size_t)(b * NPTS + j.y) * (CDIM / 4) + sub * 4;
    const float4* r2 = G4 + (size_t)(b * NPTS + j.z) * (CDIM / 4) + sub * 4;
    float4* out4 = reinterpret_cast<float4*>(out) + (size_t)q * (CDIM / 4) + sub * 4;

#pragma unroll
    for (int k = 0; k < 4; k++) {
        float4 a = __ldg(&r0[k]);
        float4 c = __ldg(&r1[k]);
        float4 e = __ldg(&r2[k]);
        float4 o;
        o.x = fmaxf(0.f, fmaf(w.x, a.x, fmaf(w.y, c.x, w.z * e.x)));
        o.y = fmaxf(0.f, fmaf(w.x, a.y, fmaf(w.y, c.y, w.z * e.y)));
        o.z = fmaxf(0.f, fmaf(w.x, a.z, fmaf(w.y, c.z, w.z * e.z)));
        o.w = fmaxf(0.f, fmaf(w.x, a.w, fmaf(w.y, c.w, w.z * e.w)));
        out4[k] = o;
    }
}

// ---------------------------------------------------------------------------
extern "C" void kernel_launch(void* const* d_in, const int* in_sizes, int n_in,
                              void* d_out, int out_size)
{
    const float* feature = (const float*)d_in[0];   // (4, 4096, 64)
    const float* pos     = (const float*)d_in[1];   // (4, 4096, 3)
    const float* pos_up  = (const float*)d_in[2];   // (4, 16384, 3)
    const float* W       = (const float*)d_in[3];   // (64, 64)
    const float* bias    = (const float*)d_in[4];   // (64,)
    float* out = (float*)d_out;                     // (4, 16384, 64)

    zero_cnt_kernel<<<500, 256>>>();
    hist_both_kernel<<<320, 256>>>(pos, pos_up);
    proj_kernel<<<BATCH * NPTS / PROJ_ROWS, 64>>>(feature, W, bias);
    scan_a_kernel<<<2 * SCANB, 1024>>>();
    scan_b_kernel<<<2, 1024>>>();
    scan_c_kernel<<<2 * SCANB, 1024>>>();
    scatter_both_kernel<<<320, 256>>>();

    query_kernel<<<BATCH * NUP / 256, 256>>>();

    apply_kernel<<<BATCH * NUP * 4 / 256, 256>>>(out);
}